// round 16
// baseline (speedup 1.0000x reference)
#include <cuda_runtime.h>
#include <cuda_fp16.h>
#include <cstdint>

// ---------------------------------------------------------------------------
// MTRNN cell as ONE block-sparse fp16 GEMM (mma.sync.m16n8k16, legacy path).
// R16 = R15 + (1) RAW-chain break: kk hoisted outer in compute_half so the
// two MMAs hitting each accumulator are 16 apart instead of back-to-back
// (HMMA fp32-acc latency >> rt; per-acc order unchanged -> bit-identical);
// (2) heavy-first blockIdx.x permutation (fast nkt=20 blocks first, out
// nkt=8 last) to shorten the straggler tail. Region-pure packed layout,
// mbarrier 3-stage pipeline, 2Mx4N warp tiling all frozen from R15.
// ---------------------------------------------------------------------------

#define BATCH 16384
#define KDIM  1344
#define NPAD  1408
#define NREAL 1344
#define NS    3

#define NT8   (NPAD / 8)         // 176
#define KT32  (KDIM / 32)        // 42
#define K16   (KDIM / 16)        // 84

#define OFF_OUT  0
#define OFF_IO   (BATCH * 64)
#define OFF_FAST (OFF_IO + BATCH * 512)
#define OFF_SLOW (OFF_FAST + BATCH * 512)

#define A_BYTES     16384
#define B_BYTES     16384
#define STAGE_BYTES (A_BYTES + B_BYTES)     // 32768
#define MB_OFF      (NS * STAGE_BYTES)      // 98304
#define SM_TOTAL    (MB_OFF + 64)

#define ABLKS 10752
#define WBLKS 3696
#define BBLKS 6

__device__ uint32_t g_Af[(size_t)BATCH * KDIM / 2];
__device__ uint32_t g_WfragH[(size_t)NT8 * KT32 * 32 * 4];
__device__ __align__(16) float g_bias[NPAD];

__device__ __forceinline__ uint32_t smem_u32(const void* p) {
    uint32_t a;
    asm("{ .reg .u64 t; cvta.to.shared.u64 t, %1; cvt.u32.u64 %0, t; }"
        : "=r"(a) : "l"(p));
    return a;
}
__device__ __forceinline__ void cpa16(uint32_t dst, const void* src) {
    asm volatile("cp.async.cg.shared.global [%0], [%1], 16;" :: "r"(dst), "l"(src));
}
__device__ __forceinline__ void mbar_init(uint32_t a, uint32_t cnt) {
    asm volatile("mbarrier.init.shared.b64 [%0], %1;" :: "r"(a), "r"(cnt) : "memory");
}
__device__ __forceinline__ void mbar_arrive(uint32_t a) {
    asm volatile("mbarrier.arrive.shared.b64 _, [%0];" :: "r"(a) : "memory");
}
__device__ __forceinline__ void cpa_mbar_arrive(uint32_t a) {
    // .noinc is load-bearing (R10 deadlock): default variant pre-increments
    // the pending count for a net-zero phase effect.
    asm volatile("cp.async.mbarrier.arrive.noinc.shared.b64 [%0];"
                 :: "r"(a) : "memory");
}
__device__ __forceinline__ void mbar_wait(uint32_t a, uint32_t parity) {
    asm volatile(
        "{\n\t.reg .pred P;\n"
        "WL_%=:\n\t"
        "mbarrier.try_wait.parity.shared.b64 P, [%0], %1;\n\t"
        "@P bra WD_%=;\n\t"
        "bra WL_%=;\n"
        "WD_%=:\n\t}"
        :: "r"(a), "r"(parity) : "memory");
}

__device__ __forceinline__ void mma_f16(float* c, uint32_t a0, uint32_t a1,
                                        uint32_t a2, uint32_t a3,
                                        uint32_t b0, uint32_t b1) {
    asm volatile(
        "mma.sync.aligned.m16n8k16.row.col.f32.f16.f16.f32 "
        "{%0,%1,%2,%3}, {%4,%5,%6,%7}, {%8,%9}, {%0,%1,%2,%3};\n"
        : "+f"(c[0]), "+f"(c[1]), "+f"(c[2]), "+f"(c[3])
        : "r"(a0), "r"(a1), "r"(a2), "r"(a3), "r"(b0), "r"(b1));
}

__device__ __forceinline__ float ftanh(float x) {
    float e = __expf(2.0f * x);
    return 1.0f - __fdividef(2.0f, e + 1.0f);
}

// packed column -> logical column of the ORIGINAL layout
__device__ __forceinline__ int packed_to_old(int pn) {
    if (pn < 512)  return 64 + pn;            // io
    if (pn < 1024) return 576 + (pn - 512);   // fast
    if (pn < 1280) return 1088 + (pn - 1024); // slow
    if (pn < 1344) return pn - 1280;          // out
    return -1;                                // pad
}

// ---------------------------------------------------------------------------
__device__ __forceinline__ float w_lookup(
    int k, int n,
    const float* W_in_io,   const float* W_io_io,   const float* W_fast_io,
    const float* W_io_fast, const float* W_fast_fast, const float* W_slow_fast,
    const float* W_fast_slow, const float* W_slow_slow, const float* W_io_out)
{
    float v = 0.0f;
    if (n < 0) return 0.0f;
    if (n < 64) {
        if (k >= 64 && k < 576)        v = W_io_out[(k - 64) * 64 + n];
    } else if (n < 576) {
        int nn = n - 64;
        if (k < 64)                    v = W_in_io[k * 512 + nn];
        else if (k < 576)              v = W_io_io[(k - 64) * 512 + nn];
        else if (k < 1088)             v = W_fast_io[(k - 576) * 512 + nn];
    } else if (n < 1088) {
        int nn = n - 576;
        if (k >= 64 && k < 576)        v = W_io_fast[(k - 64) * 512 + nn];
        else if (k >= 576 && k < 1088) v = W_fast_fast[(k - 576) * 512 + nn];
        else if (k >= 1088)            v = W_slow_fast[(k - 1088) * 512 + nn];
    } else if (n < NREAL) {
        int nn = n - 1088;
        if (k >= 576 && k < 1088)      v = W_fast_slow[(k - 576) * 256 + nn];
        else if (k >= 1088)            v = W_slow_slow[(k - 1088) * 256 + nn];
    }
    return v;
}

__global__ void prep(
    const float* __restrict__ inp,    const float* __restrict__ io_h,
    const float* __restrict__ fast_h, const float* __restrict__ slow_h,
    const float* __restrict__ W_in_io,   const float* __restrict__ W_io_io,
    const float* __restrict__ W_fast_io, const float* __restrict__ W_io_fast,
    const float* __restrict__ W_fast_fast, const float* __restrict__ W_slow_fast,
    const float* __restrict__ W_fast_slow, const float* __restrict__ W_slow_slow,
    const float* __restrict__ W_io_out,
    const float* __restrict__ b_in_io,   const float* __restrict__ b_io_io,
    const float* __restrict__ b_fast_io, const float* __restrict__ b_io_fast,
    const float* __restrict__ b_fast_fast, const float* __restrict__ b_slow_fast,
    const float* __restrict__ b_fast_slow, const float* __restrict__ b_slow_slow,
    const float* __restrict__ b_io_out)
{
    int bid = blockIdx.x;
    if (bid < ABLKS) {
        int idx     = bid * 256 + threadIdx.x;
        int lane    = idx & 31;
        int rowtile = (idx >> 5) & 7;
        int t       = idx >> 8;
        int k16     = t % K16;
        int mblk    = t / K16;
        int row = mblk * 128 + rowtile * 16 + (lane >> 2);
        int kg  = k16 * 16 + (lane & 3) * 2;
        const float* src; int ld, kb;
        if (kg < 64)        { src = inp;    ld = 64;  kb = kg; }
        else if (kg < 576)  { src = io_h;   ld = 512; kb = kg - 64; }
        else if (kg < 1088) { src = fast_h; ld = 512; kb = kg - 576; }
        else                { src = slow_h; ld = 256; kb = kg - 1088; }
        float2 p00 = *(const float2*)(src + (size_t)row * ld + kb);
        float2 p10 = *(const float2*)(src + (size_t)(row + 8) * ld + kb);
        float2 p01 = *(const float2*)(src + (size_t)row * ld + kb + 8);
        float2 p11 = *(const float2*)(src + (size_t)(row + 8) * ld + kb + 8);
        __half2 h0 = __floats2half2_rn(p00.x, p00.y);
        __half2 h1 = __floats2half2_rn(p10.x, p10.y);
        __half2 h2 = __floats2half2_rn(p01.x, p01.y);
        __half2 h3 = __floats2half2_rn(p11.x, p11.y);
        uint32_t* dst = g_Af + (((size_t)(idx >> 5) << 7) + ((idx & 31) << 2));
        *(uint4*)dst = make_uint4(*(uint32_t*)&h0, *(uint32_t*)&h1,
                                  *(uint32_t*)&h2, *(uint32_t*)&h3);
    } else if (bid < ABLKS + WBLKS) {
        int idx  = (bid - ABLKS) * 256 + threadIdx.x;
        int u    = idx & 3;
        int lane = (idx >> 2) & 31;
        int t    = idx >> 7;
        int kt32 = t % KT32;
        int nt   = t / KT32;
        int n    = packed_to_old(nt * 8 + (lane >> 2));   // region-pure perm
        int tg   = lane & 3;
        int kb   = kt32 * 32 + (u >> 1) * 16;
        int k    = kb + 2 * tg + (u & 1) * 8;
        float lo = w_lookup(k, n, W_in_io, W_io_io, W_fast_io, W_io_fast,
                            W_fast_fast, W_slow_fast, W_fast_slow, W_slow_slow,
                            W_io_out);
        float hi = w_lookup(k + 1, n, W_in_io, W_io_io, W_fast_io, W_io_fast,
                            W_fast_fast, W_slow_fast, W_fast_slow, W_slow_slow,
                            W_io_out);
        __half2 h = __floats2half2_rn(lo, hi);
        g_WfragH[idx] = *(uint32_t*)&h;
    } else {
        int pn = (bid - ABLKS - WBLKS) * 256 + threadIdx.x;
        if (pn >= NPAD) return;
        float v = 0.0f;
        if (pn < 512)        { int nn = pn;        v = b_in_io[nn] + b_io_io[nn] + b_fast_io[nn]; }
        else if (pn < 1024)  { int nn = pn - 512;  v = b_io_fast[nn] + b_fast_fast[nn] + b_slow_fast[nn]; }
        else if (pn < 1280)  { int nn = pn - 1024; v = b_slow_slow[nn] + b_fast_slow[nn]; }
        else if (pn < 1344)  { v = b_io_out[pn - 1280]; }
        g_bias[pn] = v;
    }
}

// ---------------------------------------------------------------------------
__global__ __launch_bounds__(256, 2) void mtrnn_mma(
    const float* __restrict__ io_h, const float* __restrict__ fast_h,
    const float* __restrict__ slow_h, float* __restrict__ out)
{
    extern __shared__ char smem[];
    const uint32_t sb = smem_u32(smem);

    const int tid  = threadIdx.x;
    const int lane = tid & 31;
    const int warp = tid >> 5;
    const int wm   = warp & 1;      // 0..1 : 64-row slab
    const int wn   = warp >> 1;     // 0..3 : 32-col slab

    // heavy-first launch order: fast(nkt20) -> io(17) -> slow(12) -> out(8)
    int bx = blockIdx.x;
    if (bx < 4)      bx += 4;       // launch 0..3  -> fast blocks 4..7
    else if (bx < 8) bx -= 4;       // launch 4..7  -> io blocks 0..3
    // launch 8,9 -> slow 8,9 ; launch 10 -> out 10

    const int n0 = bx * 128;
    const int m0 = blockIdx.y * 128;
    const int nt8_0 = bx * 16;

    // ---- region-pure k-range per n-block (permuted layout) ----
    int kt_lo, nkt;
    if (bx < 4)       { kt_lo = 0; nkt = 17; }   // io   : k 0..1088
    else if (bx < 8)  { kt_lo = 1; nkt = 20; }   // fast : k 64..1344
    else if (bx < 10) { kt_lo = 9; nkt = 12; }   // slow : k 576..1344
    else              { kt_lo = 1; nkt = 8;  }   // out  : k 64..576

    // ---- mbarriers: full[s]/empty[s], 256 arrivals ----
#define FULLB(S)  (sb + MB_OFF + 8 * (S))
#define EMPTYB(S) (sb + MB_OFF + 24 + 8 * (S))
    if (tid == 0) {
#pragma unroll
        for (int s = 0; s < NS; s++) { mbar_init(FULLB(s), 256); mbar_init(EMPTYB(s), 256); }
    }
    __syncthreads();

    float acc[4][4][4];
#pragma unroll
    for (int mt = 0; mt < 4; mt++)
#pragma unroll
        for (int nt = 0; nt < 4; nt++)
#pragma unroll
            for (int i = 0; i < 4; i++) acc[mt][nt][i] = 0.0f;

    // ---- walking 32-bit gmem byte offsets ----
    const char* aBase = (const char*)g_Af;
    const char* bBase = (const char*)g_WfragH;
    uint32_t aGo = ((uint32_t)blockIdx.y * K16 + (uint32_t)kt_lo * 4) * 4096
                 + (uint32_t)tid * 16;
    uint32_t bGo = (((uint32_t)(nt8_0 + (tid >> 6)) * KT32
                    + (uint32_t)kt_lo * 2 + ((tid & 63) >> 5)) * 32
                   + (tid & 31)) * 16;
    const uint32_t aSm = sb + (uint32_t)tid * 16;
    const uint32_t bSm = sb + A_BYTES + (uint32_t)tid * 16;

    auto load_slot = [&](int slot) {
        uint32_t so = (uint32_t)slot * STAGE_BYTES;
#pragma unroll
        for (int i = 0; i < 4; i++)
            cpa16(aSm + so + i * 4096, aBase + aGo + i * 4096);
#pragma unroll
        for (int i = 0; i < 4; i++)
            cpa16(bSm + so + i * 4096, bBase + bGo + (uint32_t)i * (4u * KT32 * 512u));
        aGo += 16384; bGo += 1024;
    };

    // kk-outer schedule: the two MMAs hitting each accumulator are 16 apart
    // (per-acc order still f0-then-f1 -> bit-identical results).
    auto compute_half = [&](int slot, int h) {
        const uint4*  As4 = (const uint4*)(smem + slot * STAGE_BYTES);
        const float4* Bs4 = (const float4*)(smem + slot * STAGE_BYTES + A_BYTES);
        const int kt2 = h ^ wm;                  // warp-staggered k order
        float4 bf[4];
#pragma unroll
        for (int nt = 0; nt < 4; nt++)
            bf[nt] = Bs4[((wn * 4 + nt) * 2 + kt2) * 32 + lane];
#pragma unroll
        for (int kk = 0; kk < 2; kk++) {
            uint4 f[4];
#pragma unroll
            for (int mt = 0; mt < 4; mt++)
                f[mt] = As4[((kt2 * 2 + kk) * 8 + wm * 4 + mt) * 32 + lane];
#pragma unroll
            for (int mt = 0; mt < 4; mt++) {
#pragma unroll
                for (int nt = 0; nt < 4; nt++) {
                    uint32_t b0 = kk ? __float_as_uint(bf[nt].z)
                                     : __float_as_uint(bf[nt].x);
                    uint32_t b1 = kk ? __float_as_uint(bf[nt].w)
                                     : __float_as_uint(bf[nt].y);
                    mma_f16(acc[mt][nt], f[mt].x, f[mt].y, f[mt].z, f[mt].w,
                            b0, b1);
                }
            }
        }
    };

    // ---- mbarrier-gated pipelined mainloop (slots literal via unroll-3) ----
    load_slot(0); cpa_mbar_arrive(FULLB(0));
    load_slot(1); cpa_mbar_arrive(FULLB(1));
    int ld = 2;
    uint32_t fph0 = 0, fph1 = 0, fph2 = 0;
    uint32_t eph0 = 0, eph1 = 0, eph2 = 0;

#define FPH(J)  ((J) == 0 ? fph0 : (J) == 1 ? fph1 : fph2)
#define EPH(J)  ((J) == 0 ? eph0 : (J) == 1 ? eph1 : eph2)
#define STEP(J) do {                                                    \
        mbar_wait(FULLB(J), FPH(J)); FPH(J) ^= 1;                       \
        compute_half(J, 0);                                             \
        if (ld < nkt) {                                                 \
            const int SJ = ((J) + 2) % 3;                               \
            if (ld >= 3) { mbar_wait(EMPTYB(SJ), EPH(SJ)); EPH(SJ) ^= 1; } \
            load_slot(SJ); cpa_mbar_arrive(FULLB(SJ));                  \
        }                                                               \
        compute_half(J, 1);                                             \
        mbar_arrive(EMPTYB(J));                                         \
        ld++;                                                           \
    } while (0)

    int it = 0;
    while (it + 3 <= nkt) { STEP(0); STEP(1); STEP(2); it += 3; }
    if (it < nkt) { STEP(0); it++; }
    if (it < nkt) { STEP(1); it++; }
#undef STEP
#undef FPH
#undef EPH

    // ---- epilogue: bias + leak + tanh, float2 stores (permuted regions) ----
    const int eg  = lane >> 2;
    const int etg = lane & 3;
#pragma unroll
    for (int nt = 0; nt < 4; nt++) {
        int gb = n0 + wn * 32 + nt * 8;
        if (gb >= NREAL) continue;               // pad cols (block 10 upper)
        int gn = gb + etg * 2;
        float2 bi = *(const float2*)&g_bias[gn];
#pragma unroll
        for (int mt = 0; mt < 4; mt++) {
            int br = m0 + wm * 64 + mt * 16 + eg;
#pragma unroll
            for (int hh = 0; hh < 2; hh++) {
                int b = br + hh * 8;
                float s0 = acc[mt][nt][hh * 2 + 0] + bi.x;
                float s1 = acc[mt][nt][hh * 2 + 1] + bi.y;
                float2 o;
                if (gb < 512) {                              // io
                    int nn = gn;
                    float2 h = *(const float2*)&io_h[(size_t)b * 512 + nn];
                    o.x = ftanh(0.5f * h.x + 0.5f * s0);
                    o.y = ftanh(0.5f * h.y + 0.5f * s1);
                    *(float2*)&out[OFF_IO + (size_t)b * 512 + nn] = o;
                } else if (gb < 1024) {                      // fast
                    int nn = gn - 512;
                    float2 h = *(const float2*)&fast_h[(size_t)b * 512 + nn];
                    o.x = ftanh(0.8f * h.x + 0.2f * s0);
                    o.y = ftanh(0.8f * h.y + 0.2f * s1);
                    *(float2*)&out[OFF_FAST + (size_t)b * 512 + nn] = o;
                } else if (gb < 1280) {                      // slow
                    int nn = gn - 1024;
                    const float cs = 1.0f - 1.0f / 70.0f, is = 1.0f / 70.0f;
                    float2 h = *(const float2*)&slow_h[(size_t)b * 256 + nn];
                    o.x = ftanh(cs * h.x + is * s0);
                    o.y = ftanh(cs * h.y + is * s1);
                    *(float2*)&out[OFF_SLOW + (size_t)b * 256 + nn] = o;
                } else {                                     // out
                    int nn = gn - 1280;
                    o.x = ftanh(s0); o.y = ftanh(s1);
                    *(float2*)&out[OFF_OUT + (size_t)b * 64 + nn] = o;
                }
            }
        }
    }
}

// ---------------------------------------------------------------------------
extern "C" void kernel_launch(void* const* d_in, const int* in_sizes, int n_in,
                              void* d_out, int out_size)
{
    const float* input       = (const float*)d_in[0];
    const float* io_h        = (const float*)d_in[1];
    const float* fast_h      = (const float*)d_in[2];
    const float* slow_h      = (const float*)d_in[3];
    const float* W_in_io     = (const float*)d_in[4];
    const float* b_in_io     = (const float*)d_in[5];
    const float* W_io_fast   = (const float*)d_in[6];
    const float* b_io_fast   = (const float*)d_in[7];
    const float* W_fast_fast = (const float*)d_in[8];
    const float* b_fast_fast = (const float*)d_in[9];
    const float* W_fast_slow = (const float*)d_in[10];
    const float* b_fast_slow = (const float*)d_in[11];
    const float* W_slow_slow = (const float*)d_in[12];
    const float* b_slow_slow = (const float*)d_in[13];
    const float* W_slow_fast = (const float*)d_in[14];
    const float* b_slow_fast = (const float*)d_in[15];
    const float* W_fast_io   = (const float*)d_in[16];
    const float* b_fast_io   = (const float*)d_in[17];
    const float* W_io_io     = (const float*)d_in[18];
    const float* b_io_io     = (const float*)d_in[19];
    const float* W_io_out    = (const float*)d_in[20];
    const float* b_io_out    = (const float*)d_in[21];

    cudaFuncSetAttribute(mtrnn_mma, cudaFuncAttributeMaxDynamicSharedMemorySize,
                         SM_TOTAL);

    prep<<<ABLKS + WBLKS + BBLKS, 256>>>(
        input, io_h, fast_h, slow_h,
        W_in_io, W_io_io, W_fast_io, W_io_fast, W_fast_fast,
        W_slow_fast, W_fast_slow, W_slow_slow, W_io_out,
        b_in_io, b_io_io, b_fast_io, b_io_fast, b_fast_fast,
        b_slow_fast, b_fast_slow, b_slow_slow, b_io_out);

    dim3 grid(NPAD / 128, BATCH / 128);
    mtrnn_mma<<<grid, 256, SM_TOTAL>>>(io_h, fast_h, slow_h, (float*)d_out);
}

// round 17
// speedup vs baseline: 1.0071x; 1.0071x over previous
#include <cuda_runtime.h>
#include <cuda_fp16.h>
#include <cstdint>

// ---------------------------------------------------------------------------
// MTRNN cell as ONE block-sparse fp16 GEMM (mma.sync.m16n8k16, legacy path).
// R17 = R15 exactly (R16's kk-outer + heavy-first reverted: -4us GEMM) with
// ONE minimal change: within each mt, issue the four f0-MMAs (nt=0..3) then
// the four f1-MMAs. Acc reuse distance 1 -> 4 MMAs (~58cyc > HMMA latency),
// loads and register liveness untouched, per-acc order f0-then-f1 preserved
// -> bit-identical (rel_err must stay 3.065842e-4). Region-pure layout,
// mbarrier 3-stage pipeline, 2Mx4N warp tiling all frozen.
// ---------------------------------------------------------------------------

#define BATCH 16384
#define KDIM  1344
#define NPAD  1408
#define NREAL 1344
#define NS    3

#define NT8   (NPAD / 8)         // 176
#define KT32  (KDIM / 32)        // 42
#define K16   (KDIM / 16)        // 84

#define OFF_OUT  0
#define OFF_IO   (BATCH * 64)
#define OFF_FAST (OFF_IO + BATCH * 512)
#define OFF_SLOW (OFF_FAST + BATCH * 512)

#define A_BYTES     16384
#define B_BYTES     16384
#define STAGE_BYTES (A_BYTES + B_BYTES)     // 32768
#define MB_OFF      (NS * STAGE_BYTES)      // 98304
#define SM_TOTAL    (MB_OFF + 64)

#define ABLKS 10752
#define WBLKS 3696
#define BBLKS 6

__device__ uint32_t g_Af[(size_t)BATCH * KDIM / 2];
__device__ uint32_t g_WfragH[(size_t)NT8 * KT32 * 32 * 4];
__device__ __align__(16) float g_bias[NPAD];

__device__ __forceinline__ uint32_t smem_u32(const void* p) {
    uint32_t a;
    asm("{ .reg .u64 t; cvta.to.shared.u64 t, %1; cvt.u32.u64 %0, t; }"
        : "=r"(a) : "l"(p));
    return a;
}
__device__ __forceinline__ void cpa16(uint32_t dst, const void* src) {
    asm volatile("cp.async.cg.shared.global [%0], [%1], 16;" :: "r"(dst), "l"(src));
}
__device__ __forceinline__ void mbar_init(uint32_t a, uint32_t cnt) {
    asm volatile("mbarrier.init.shared.b64 [%0], %1;" :: "r"(a), "r"(cnt) : "memory");
}
__device__ __forceinline__ void mbar_arrive(uint32_t a) {
    asm volatile("mbarrier.arrive.shared.b64 _, [%0];" :: "r"(a) : "memory");
}
__device__ __forceinline__ void cpa_mbar_arrive(uint32_t a) {
    // .noinc is load-bearing (R10 deadlock): default variant pre-increments
    // the pending count for a net-zero phase effect.
    asm volatile("cp.async.mbarrier.arrive.noinc.shared.b64 [%0];"
                 :: "r"(a) : "memory");
}
__device__ __forceinline__ void mbar_wait(uint32_t a, uint32_t parity) {
    asm volatile(
        "{\n\t.reg .pred P;\n"
        "WL_%=:\n\t"
        "mbarrier.try_wait.parity.shared.b64 P, [%0], %1;\n\t"
        "@P bra WD_%=;\n\t"
        "bra WL_%=;\n"
        "WD_%=:\n\t}"
        :: "r"(a), "r"(parity) : "memory");
}

__device__ __forceinline__ void mma_f16(float* c, uint32_t a0, uint32_t a1,
                                        uint32_t a2, uint32_t a3,
                                        uint32_t b0, uint32_t b1) {
    asm volatile(
        "mma.sync.aligned.m16n8k16.row.col.f32.f16.f16.f32 "
        "{%0,%1,%2,%3}, {%4,%5,%6,%7}, {%8,%9}, {%0,%1,%2,%3};\n"
        : "+f"(c[0]), "+f"(c[1]), "+f"(c[2]), "+f"(c[3])
        : "r"(a0), "r"(a1), "r"(a2), "r"(a3), "r"(b0), "r"(b1));
}

__device__ __forceinline__ float ftanh(float x) {
    float e = __expf(2.0f * x);
    return 1.0f - __fdividef(2.0f, e + 1.0f);
}

// packed column -> logical column of the ORIGINAL layout
__device__ __forceinline__ int packed_to_old(int pn) {
    if (pn < 512)  return 64 + pn;            // io
    if (pn < 1024) return 576 + (pn - 512);   // fast
    if (pn < 1280) return 1088 + (pn - 1024); // slow
    if (pn < 1344) return pn - 1280;          // out
    return -1;                                // pad
}

// ---------------------------------------------------------------------------
__device__ __forceinline__ float w_lookup(
    int k, int n,
    const float* W_in_io,   const float* W_io_io,   const float* W_fast_io,
    const float* W_io_fast, const float* W_fast_fast, const float* W_slow_fast,
    const float* W_fast_slow, const float* W_slow_slow, const float* W_io_out)
{
    float v = 0.0f;
    if (n < 0) return 0.0f;
    if (n < 64) {
        if (k >= 64 && k < 576)        v = W_io_out[(k - 64) * 64 + n];
    } else if (n < 576) {
        int nn = n - 64;
        if (k < 64)                    v = W_in_io[k * 512 + nn];
        else if (k < 576)              v = W_io_io[(k - 64) * 512 + nn];
        else if (k < 1088)             v = W_fast_io[(k - 576) * 512 + nn];
    } else if (n < 1088) {
        int nn = n - 576;
        if (k >= 64 && k < 576)        v = W_io_fast[(k - 64) * 512 + nn];
        else if (k >= 576 && k < 1088) v = W_fast_fast[(k - 576) * 512 + nn];
        else if (k >= 1088)            v = W_slow_fast[(k - 1088) * 512 + nn];
    } else if (n < NREAL) {
        int nn = n - 1088;
        if (k >= 576 && k < 1088)      v = W_fast_slow[(k - 576) * 256 + nn];
        else if (k >= 1088)            v = W_slow_slow[(k - 1088) * 256 + nn];
    }
    return v;
}

__global__ void prep(
    const float* __restrict__ inp,    const float* __restrict__ io_h,
    const float* __restrict__ fast_h, const float* __restrict__ slow_h,
    const float* __restrict__ W_in_io,   const float* __restrict__ W_io_io,
    const float* __restrict__ W_fast_io, const float* __restrict__ W_io_fast,
    const float* __restrict__ W_fast_fast, const float* __restrict__ W_slow_fast,
    const float* __restrict__ W_fast_slow, const float* __restrict__ W_slow_slow,
    const float* __restrict__ W_io_out,
    const float* __restrict__ b_in_io,   const float* __restrict__ b_io_io,
    const float* __restrict__ b_fast_io, const float* __restrict__ b_io_fast,
    const float* __restrict__ b_fast_fast, const float* __restrict__ b_slow_fast,
    const float* __restrict__ b_fast_slow, const float* __restrict__ b_slow_slow,
    const float* __restrict__ b_io_out)
{
    int bid = blockIdx.x;
    if (bid < ABLKS) {
        int idx     = bid * 256 + threadIdx.x;
        int lane    = idx & 31;
        int rowtile = (idx >> 5) & 7;
        int t       = idx >> 8;
        int k16     = t % K16;
        int mblk    = t / K16;
        int row = mblk * 128 + rowtile * 16 + (lane >> 2);
        int kg  = k16 * 16 + (lane & 3) * 2;
        const float* src; int ld, kb;
        if (kg < 64)        { src = inp;    ld = 64;  kb = kg; }
        else if (kg < 576)  { src = io_h;   ld = 512; kb = kg - 64; }
        else if (kg < 1088) { src = fast_h; ld = 512; kb = kg - 576; }
        else                { src = slow_h; ld = 256; kb = kg - 1088; }
        float2 p00 = *(const float2*)(src + (size_t)row * ld + kb);
        float2 p10 = *(const float2*)(src + (size_t)(row + 8) * ld + kb);
        float2 p01 = *(const float2*)(src + (size_t)row * ld + kb + 8);
        float2 p11 = *(const float2*)(src + (size_t)(row + 8) * ld + kb + 8);
        __half2 h0 = __floats2half2_rn(p00.x, p00.y);
        __half2 h1 = __floats2half2_rn(p10.x, p10.y);
        __half2 h2 = __floats2half2_rn(p01.x, p01.y);
        __half2 h3 = __floats2half2_rn(p11.x, p11.y);
        uint32_t* dst = g_Af + (((size_t)(idx >> 5) << 7) + ((idx & 31) << 2));
        *(uint4*)dst = make_uint4(*(uint32_t*)&h0, *(uint32_t*)&h1,
                                  *(uint32_t*)&h2, *(uint32_t*)&h3);
    } else if (bid < ABLKS + WBLKS) {
        int idx  = (bid - ABLKS) * 256 + threadIdx.x;
        int u    = idx & 3;
        int lane = (idx >> 2) & 31;
        int t    = idx >> 7;
        int kt32 = t % KT32;
        int nt   = t / KT32;
        int n    = packed_to_old(nt * 8 + (lane >> 2));   // region-pure perm
        int tg   = lane & 3;
        int kb   = kt32 * 32 + (u >> 1) * 16;
        int k    = kb + 2 * tg + (u & 1) * 8;
        float lo = w_lookup(k, n, W_in_io, W_io_io, W_fast_io, W_io_fast,
                            W_fast_fast, W_slow_fast, W_fast_slow, W_slow_slow,
                            W_io_out);
        float hi = w_lookup(k + 1, n, W_in_io, W_io_io, W_fast_io, W_io_fast,
                            W_fast_fast, W_slow_fast, W_fast_slow, W_slow_slow,
                            W_io_out);
        __half2 h = __floats2half2_rn(lo, hi);
        g_WfragH[idx] = *(uint32_t*)&h;
    } else {
        int pn = (bid - ABLKS - WBLKS) * 256 + threadIdx.x;
        if (pn >= NPAD) return;
        float v = 0.0f;
        if (pn < 512)        { int nn = pn;        v = b_in_io[nn] + b_io_io[nn] + b_fast_io[nn]; }
        else if (pn < 1024)  { int nn = pn - 512;  v = b_io_fast[nn] + b_fast_fast[nn] + b_slow_fast[nn]; }
        else if (pn < 1280)  { int nn = pn - 1024; v = b_slow_slow[nn] + b_fast_slow[nn]; }
        else if (pn < 1344)  { v = b_io_out[pn - 1280]; }
        g_bias[pn] = v;
    }
}

// ---------------------------------------------------------------------------
__global__ __launch_bounds__(256, 2) void mtrnn_mma(
    const float* __restrict__ io_h, const float* __restrict__ fast_h,
    const float* __restrict__ slow_h, float* __restrict__ out)
{
    extern __shared__ char smem[];
    const uint32_t sb = smem_u32(smem);

    const int tid  = threadIdx.x;
    const int lane = tid & 31;
    const int warp = tid >> 5;
    const int wm   = warp & 1;      // 0..1 : 64-row slab
    const int wn   = warp >> 1;     // 0..3 : 32-col slab

    const int n0 = blockIdx.x * 128;
    const int m0 = blockIdx.y * 128;
    const int nt8_0 = blockIdx.x * 16;

    // ---- region-pure k-range per n-block (permuted layout) ----
    int kt_lo, nkt;
    {
        int bx = blockIdx.x;
        if (bx < 4)       { kt_lo = 0; nkt = 17; }   // io   : k 0..1088
        else if (bx < 8)  { kt_lo = 1; nkt = 20; }   // fast : k 64..1344
        else if (bx < 10) { kt_lo = 9; nkt = 12; }   // slow : k 576..1344
        else              { kt_lo = 1; nkt = 8;  }   // out  : k 64..576
    }

    // ---- mbarriers: full[s]/empty[s], 256 arrivals ----
#define FULLB(S)  (sb + MB_OFF + 8 * (S))
#define EMPTYB(S) (sb + MB_OFF + 24 + 8 * (S))
    if (tid == 0) {
#pragma unroll
        for (int s = 0; s < NS; s++) { mbar_init(FULLB(s), 256); mbar_init(EMPTYB(s), 256); }
    }
    __syncthreads();

    float acc[4][4][4];
#pragma unroll
    for (int mt = 0; mt < 4; mt++)
#pragma unroll
        for (int nt = 0; nt < 4; nt++)
#pragma unroll
            for (int i = 0; i < 4; i++) acc[mt][nt][i] = 0.0f;

    // ---- walking 32-bit gmem byte offsets ----
    const char* aBase = (const char*)g_Af;
    const char* bBase = (const char*)g_WfragH;
    uint32_t aGo = ((uint32_t)blockIdx.y * K16 + (uint32_t)kt_lo * 4) * 4096
                 + (uint32_t)tid * 16;
    uint32_t bGo = (((uint32_t)(nt8_0 + (tid >> 6)) * KT32
                    + (uint32_t)kt_lo * 2 + ((tid & 63) >> 5)) * 32
                   + (tid & 31)) * 16;
    const uint32_t aSm = sb + (uint32_t)tid * 16;
    const uint32_t bSm = sb + A_BYTES + (uint32_t)tid * 16;

    auto load_slot = [&](int slot) {
        uint32_t so = (uint32_t)slot * STAGE_BYTES;
#pragma unroll
        for (int i = 0; i < 4; i++)
            cpa16(aSm + so + i * 4096, aBase + aGo + i * 4096);
#pragma unroll
        for (int i = 0; i < 4; i++)
            cpa16(bSm + so + i * 4096, bBase + bGo + (uint32_t)i * (4u * KT32 * 512u));
        aGo += 16384; bGo += 1024;
    };

    // R15 loads; MMA issue nt-batched: per mt, four f0-MMAs then four f1-MMAs
    // (acc reuse distance 1 -> 4; per-acc order f0-then-f1 -> bit-identical).
    auto compute_half = [&](int slot, int h) {
        const uint4*  As4 = (const uint4*)(smem + slot * STAGE_BYTES);
        const float4* Bs4 = (const float4*)(smem + slot * STAGE_BYTES + A_BYTES);
        const int kt2 = h ^ wm;                  // warp-staggered k order
        float4 bf[4];
#pragma unroll
        for (int nt = 0; nt < 4; nt++)
            bf[nt] = Bs4[((wn * 4 + nt) * 2 + kt2) * 32 + lane];
#pragma unroll
        for (int mt = 0; mt < 4; mt++) {
            uint4 f0 = As4[((kt2 * 2 + 0) * 8 + wm * 4 + mt) * 32 + lane];
            uint4 f1 = As4[((kt2 * 2 + 1) * 8 + wm * 4 + mt) * 32 + lane];
#pragma unroll
            for (int nt = 0; nt < 4; nt++)
                mma_f16(acc[mt][nt], f0.x, f0.y, f0.z, f0.w,
                        __float_as_uint(bf[nt].x), __float_as_uint(bf[nt].y));
#pragma unroll
            for (int nt = 0; nt < 4; nt++)
                mma_f16(acc[mt][nt], f1.x, f1.y, f1.z, f1.w,
                        __float_as_uint(bf[nt].z), __float_as_uint(bf[nt].w));
        }
    };

    // ---- mbarrier-gated pipelined mainloop (slots literal via unroll-3) ----
    load_slot(0); cpa_mbar_arrive(FULLB(0));
    load_slot(1); cpa_mbar_arrive(FULLB(1));
    int ld = 2;
    uint32_t fph0 = 0, fph1 = 0, fph2 = 0;
    uint32_t eph0 = 0, eph1 = 0, eph2 = 0;

#define FPH(J)  ((J) == 0 ? fph0 : (J) == 1 ? fph1 : fph2)
#define EPH(J)  ((J) == 0 ? eph0 : (J) == 1 ? eph1 : eph2)
#define STEP(J) do {                                                    \
        mbar_wait(FULLB(J), FPH(J)); FPH(J) ^= 1;                       \
        compute_half(J, 0);                                             \
        if (ld < nkt) {                                                 \
            const int SJ = ((J) + 2) % 3;                               \
            if (ld >= 3) { mbar_wait(EMPTYB(SJ), EPH(SJ)); EPH(SJ) ^= 1; } \
            load_slot(SJ); cpa_mbar_arrive(FULLB(SJ));                  \
        }                                                               \
        compute_half(J, 1);                                             \
        mbar_arrive(EMPTYB(J));                                         \
        ld++;                                                           \
    } while (0)

    int it = 0;
    while (it + 3 <= nkt) { STEP(0); STEP(1); STEP(2); it += 3; }
    if (it < nkt) { STEP(0); it++; }
    if (it < nkt) { STEP(1); it++; }
#undef STEP
#undef FPH
#undef EPH

    // ---- epilogue: bias + leak + tanh, float2 stores (permuted regions) ----
    const int eg  = lane >> 2;
    const int etg = lane & 3;
#pragma unroll
    for (int nt = 0; nt < 4; nt++) {
        int gb = n0 + wn * 32 + nt * 8;
        if (gb >= NREAL) continue;               // pad cols (block 10 upper)
        int gn = gb + etg * 2;
        float2 bi = *(const float2*)&g_bias[gn];
#pragma unroll
        for (int mt = 0; mt < 4; mt++) {
            int br = m0 + wm * 64 + mt * 16 + eg;
#pragma unroll
            for (int hh = 0; hh < 2; hh++) {
                int b = br + hh * 8;
                float s0 = acc[mt][nt][hh * 2 + 0] + bi.x;
                float s1 = acc[mt][nt][hh * 2 + 1] + bi.y;
                float2 o;
                if (gb < 512) {                              // io
                    int nn = gn;
                    float2 h = *(const float2*)&io_h[(size_t)b * 512 + nn];
                    o.x = ftanh(0.5f * h.x + 0.5f * s0);
                    o.y = ftanh(0.5f * h.y + 0.5f * s1);
                    *(float2*)&out[OFF_IO + (size_t)b * 512 + nn] = o;
                } else if (gb < 1024) {                      // fast
                    int nn = gn - 512;
                    float2 h = *(const float2*)&fast_h[(size_t)b * 512 + nn];
                    o.x = ftanh(0.8f * h.x + 0.2f * s0);
                    o.y = ftanh(0.8f * h.y + 0.2f * s1);
                    *(float2*)&out[OFF_FAST + (size_t)b * 512 + nn] = o;
                } else if (gb < 1280) {                      // slow
                    int nn = gn - 1024;
                    const float cs = 1.0f - 1.0f / 70.0f, is = 1.0f / 70.0f;
                    float2 h = *(const float2*)&slow_h[(size_t)b * 256 + nn];
                    o.x = ftanh(cs * h.x + is * s0);
                    o.y = ftanh(cs * h.y + is * s1);
                    *(float2*)&out[OFF_SLOW + (size_t)b * 256 + nn] = o;
                } else {                                     // out
                    int nn = gn - 1280;
                    o.x = ftanh(s0); o.y = ftanh(s1);
                    *(float2*)&out[OFF_OUT + (size_t)b * 64 + nn] = o;
                }
            }
        }
    }
}

// ---------------------------------------------------------------------------
extern "C" void kernel_launch(void* const* d_in, const int* in_sizes, int n_in,
                              void* d_out, int out_size)
{
    const float* input       = (const float*)d_in[0];
    const float* io_h        = (const float*)d_in[1];
    const float* fast_h      = (const float*)d_in[2];
    const float* slow_h      = (const float*)d_in[3];
    const float* W_in_io     = (const float*)d_in[4];
    const float* b_in_io     = (const float*)d_in[5];
    const float* W_io_fast   = (const float*)d_in[6];
    const float* b_io_fast   = (const float*)d_in[7];
    const float* W_fast_fast = (const float*)d_in[8];
    const float* b_fast_fast = (const float*)d_in[9];
    const float* W_fast_slow = (const float*)d_in[10];
    const float* b_fast_slow = (const float*)d_in[11];
    const float* W_slow_slow = (const float*)d_in[12];
    const float* b_slow_slow = (const float*)d_in[13];
    const float* W_slow_fast = (const float*)d_in[14];
    const float* b_slow_fast = (const float*)d_in[15];
    const float* W_fast_io   = (const float*)d_in[16];
    const float* b_fast_io   = (const float*)d_in[17];
    const float* W_io_io     = (const float*)d_in[18];
    const float* b_io_io     = (const float*)d_in[19];
    const float* W_io_out    = (const float*)d_in[20];
    const float* b_io_out    = (const float*)d_in[21];

    cudaFuncSetAttribute(mtrnn_mma, cudaFuncAttributeMaxDynamicSharedMemorySize,
                         SM_TOTAL);

    prep<<<ABLKS + WBLKS + BBLKS, 256>>>(
        input, io_h, fast_h, slow_h,
        W_in_io, W_io_io, W_fast_io, W_io_fast, W_fast_fast,
        W_slow_fast, W_fast_slow, W_slow_slow, W_io_out,
        b_in_io, b_io_io, b_fast_io, b_io_fast, b_fast_fast,
        b_slow_fast, b_fast_slow, b_slow_slow, b_io_out);

    dim3 grid(NPAD / 128, BATCH / 128);
    mtrnn_mma<<<grid, 256, SM_TOTAL>>>(io_h, fast_h, slow_h, (float*)d_out);
}